// round 5
// baseline (speedup 1.0000x reference)
#include <cuda_runtime.h>
#include <math.h>
#include <stdint.h>

// ---------------------------------------------------------------------------
// TemporalMamba: x -> in_proj -> 4x Mamba blocks -> LN(last token) -> out_proj
// All fp32. GEMMs: 128x128x8 register-blocked SGEMM with deterministic K-split
// (partials + reduce), scan: 16 lanes per (batch, channel) with shfl reduce.
// ---------------------------------------------------------------------------

#define IN_DIM_ 16384
#define DM_     512
#define DEPTH_  4
#define DI_     1024
#define DS_     16
#define DC_     4
#define DR_     32
#define B_      4
#define L_      256
#define T_      (B_ * L_)          // 1024 tokens
#define XPD_    (DR_ + 2 * DS_)    // 64

// Scratch (device globals: no allocation allowed)
__device__ float g_h[T_ * DM_];            // hidden  [1024, 512]
__device__ float g_xz[T_ * 2 * DI_];       // in-proj of block [1024, 2048]
__device__ float g_xc[T_ * DI_];           // conv+silu output [1024, 1024]
__device__ float g_xdbl[T_ * XPD_];        // x-proj [1024, 64]
__device__ float g_dt[T_ * DI_];           // softplus(dt) [1024, 1024]
__device__ float g_y[T_ * DI_];            // scan output [1024, 1024]
__device__ float g_hn[B_ * DM_];           // layernormed last tokens [4, 512]
__device__ float g_part[16 * T_ * DM_];    // K-split partials (max 16 x 1024 x 512)

// ---------------------------------------------------------------------------
// Generic C = A * W^T  (A: [M,K] row-major, W: [N,K] row-major).
// Block tile 128x128, BK=8, 256 threads, 8x8 per-thread microtile,
// single-stage smem with global prefetch. gridDim.z = K-split; each z writes
// its partial tile to C + z*M*N (deterministic; reduced by reduce_kernel).
// ---------------------------------------------------------------------------
__global__ __launch_bounds__(256) void sgemm_atb(
    const float* __restrict__ A, const float* __restrict__ W,
    float* __restrict__ C, int M, int N, int K, int kchunk)
{
    __shared__ float As[8][128];
    __shared__ float Bs[8][128];

    const int tid = threadIdx.x;
    const int tx  = tid & 15;
    const int ty  = tid >> 4;
    const int m0  = blockIdx.y * 128;
    const int n0  = blockIdx.x * 128;
    const int k0  = blockIdx.z * kchunk;
    const int k1  = min(K, k0 + kchunk);

    const int  lrow  = tid >> 1;          // 0..127
    const int  lk    = (tid & 1) * 4;     // 0 or 4
    const bool wv_ok = (n0 + lrow) < N;
    const float* Ap  = A + (size_t)(m0 + lrow) * K + lk;
    const float* Wp  = W + (size_t)(n0 + lrow) * K + lk;

    float acc[8][8];
#pragma unroll
    for (int i = 0; i < 8; i++)
#pragma unroll
        for (int j = 0; j < 8; j++) acc[i][j] = 0.f;

    float4 av = *(const float4*)(Ap + k0);
    float4 wv = wv_ok ? *(const float4*)(Wp + k0) : make_float4(0.f, 0.f, 0.f, 0.f);

    for (int k = k0; k < k1; k += 8) {
        __syncthreads();
        As[lk + 0][lrow] = av.x; As[lk + 1][lrow] = av.y;
        As[lk + 2][lrow] = av.z; As[lk + 3][lrow] = av.w;
        Bs[lk + 0][lrow] = wv.x; Bs[lk + 1][lrow] = wv.y;
        Bs[lk + 2][lrow] = wv.z; Bs[lk + 3][lrow] = wv.w;
        __syncthreads();

        if (k + 8 < k1) {   // prefetch next tile while computing this one
            av = *(const float4*)(Ap + k + 8);
            wv = wv_ok ? *(const float4*)(Wp + k + 8) : make_float4(0.f, 0.f, 0.f, 0.f);
        }

#pragma unroll
        for (int kk = 0; kk < 8; kk++) {
            float a[8], b[8];
            *(float4*)(a)     = *(const float4*)(&As[kk][ty * 8]);
            *(float4*)(a + 4) = *(const float4*)(&As[kk][ty * 8 + 4]);
            *(float4*)(b)     = *(const float4*)(&Bs[kk][tx * 8]);
            *(float4*)(b + 4) = *(const float4*)(&Bs[kk][tx * 8 + 4]);
#pragma unroll
            for (int i = 0; i < 8; i++)
#pragma unroll
                for (int j = 0; j < 8; j++)
                    acc[i][j] += a[i] * b[j];
        }
    }

    float* Cp = C + (size_t)blockIdx.z * M * N;
#pragma unroll
    for (int i = 0; i < 8; i++) {
        const int row = m0 + ty * 8 + i;
#pragma unroll
        for (int j = 0; j < 8; j += 4) {
            const int col = n0 + tx * 8 + j;
            if (col < N) {
                *(float4*)(&Cp[(size_t)row * N + col]) =
                    make_float4(acc[i][j], acc[i][j + 1], acc[i][j + 2], acc[i][j + 3]);
            }
        }
    }
}

// Sum ks partials (deterministic order) + optional per-column bias.
__global__ void reduce_kernel(const float* __restrict__ P, float* __restrict__ C,
                              int MN, int ks, const float* __restrict__ bias, int N)
{
    const int i = blockIdx.x * 256 + threadIdx.x;
    if (i >= MN) return;
    float s = 0.f;
    for (int z = 0; z < ks; z++) s += P[(size_t)z * MN + i];
    if (bias) s += bias[i % N];
    C[i] = s;
}

// Causal depthwise conv (width 4) + SiLU on xc = g_xz[:, :DI]
__global__ void conv_silu_kernel(const float* __restrict__ cw, const float* __restrict__ cb)
{
    const int idx = blockIdx.x * 256 + threadIdx.x;   // T_*DI_ threads
    const int c = idx & (DI_ - 1);
    const int t = idx >> 10;
    const int b = t >> 8;
    const int l = t & (L_ - 1);
    float acc = cb[c];
#pragma unroll
    for (int k = 0; k < DC_; k++) {
        const int ls = l - (DC_ - 1) + k;
        if (ls >= 0)
            acc += g_xz[(size_t)((b << 8) + ls) * (2 * DI_) + c] * cw[c * DC_ + k];
    }
    g_xc[idx] = acc / (1.f + expf(-acc));   // silu
}

// dt[t,d] = softplus( xdbl[t, :32] . dt_w[d, :] + dt_b[d] )
__global__ void dt_kernel(const float* __restrict__ dw, const float* __restrict__ db)
{
    __shared__ float sx[DR_];
    const int t = blockIdx.y;
    const int d = blockIdx.x * 256 + threadIdx.x;
    if (threadIdx.x < DR_) sx[threadIdx.x] = g_xdbl[t * XPD_ + threadIdx.x];
    __syncthreads();
    float acc = db[d];
    const float4* w4 = (const float4*)(dw + (size_t)d * DR_);
#pragma unroll
    for (int r = 0; r < DR_ / 4; r++) {
        const float4 w = w4[r];
        acc += sx[4 * r] * w.x + sx[4 * r + 1] * w.y +
               sx[4 * r + 2] * w.z + sx[4 * r + 3] * w.w;
    }
    const float sp = (acc > 20.f) ? acc : log1pf(expf(acc));
    g_dt[t * DI_ + d] = sp;
}

// Selective scan. 16 lanes per (b,d) pair: lane n owns state n (n<16).
// Per step: state = exp(dt*A_n)*state + (dt*xc)*B_n; y = sum_n state*C_n
// (4-round shfl-xor within the 16-lane group), epilogue y = (y + xc*D)*silu(z).
__global__ void scan_kernel(const float* __restrict__ Alog, const float* __restrict__ Dp)
{
    const int lane = threadIdx.x & 31;
    const int n    = lane & 15;
    const int p    = (((blockIdx.x * 256 + threadIdx.x) >> 5) << 1) + (lane >> 4);
    const int b    = p >> 10;           // / DI_
    const int d    = p & (DI_ - 1);

    const float A   = -expf(Alog[d * DS_ + n]);
    const float Dpd = Dp[d];
    float s = 0.f;

    for (int l = 0; l < L_; l++) {
        const int t = (b << 8) + l;
        const float dtv = g_dt[t * DI_ + d];
        const float xv  = g_xc[t * DI_ + d];
        const float q   = __expf(dtv * A);
        const float bm  = g_xdbl[t * XPD_ + DR_ + n];
        s = q * s + (dtv * xv) * bm;
        float v = s * g_xdbl[t * XPD_ + DR_ + DS_ + n];
        v += __shfl_xor_sync(0xFFFFFFFFu, v, 8);
        v += __shfl_xor_sync(0xFFFFFFFFu, v, 4);
        v += __shfl_xor_sync(0xFFFFFFFFu, v, 2);
        v += __shfl_xor_sync(0xFFFFFFFFu, v, 1);
        if (n == 0) {
            const float zv = g_xz[(size_t)t * (2 * DI_) + DI_ + d];
            const float yy = v + xv * Dpd;
            g_y[t * DI_ + d] = yy * (zv / (1.f + expf(-zv)));
        }
    }
}

// LayerNorm over last token of each batch
__global__ void ln_kernel(const float* __restrict__ gamma, const float* __restrict__ beta)
{
    __shared__ float red[128];
    const int b   = blockIdx.x;
    const int tid = threadIdx.x;   // 128
    const float* row = g_h + (size_t)((b + 1) * L_ - 1) * DM_;

    float v[4]; float s = 0.f;
#pragma unroll
    for (int i = 0; i < 4; i++) { v[i] = row[tid + i * 128]; s += v[i]; }
    red[tid] = s; __syncthreads();
    for (int o = 64; o > 0; o >>= 1) { if (tid < o) red[tid] += red[tid + o]; __syncthreads(); }
    const float mu = red[0] * (1.f / DM_);
    __syncthreads();

    float var = 0.f;
#pragma unroll
    for (int i = 0; i < 4; i++) { const float dd = v[i] - mu; var += dd * dd; }
    red[tid] = var; __syncthreads();
    for (int o = 64; o > 0; o >>= 1) { if (tid < o) red[tid] += red[tid + o]; __syncthreads(); }
    const float rstd = rsqrtf(red[0] * (1.f / DM_) + 1e-5f);

#pragma unroll
    for (int i = 0; i < 4; i++) {
        const int m = tid + i * 128;
        g_hn[b * DM_ + m] = (v[i] - mu) * rstd * gamma[m] + beta[m];
    }
}

// out[b, o] = hn[b,:] . out_w[o,:] + out_b[o]; one thread per o, all 4 batches
// share each out_w row read (32MB streamed once).
__global__ void outproj_kernel(const float* __restrict__ ow, const float* __restrict__ ob,
                               float* __restrict__ out)
{
    __shared__ float sh[B_ * DM_];
    const int tid = threadIdx.x;  // 128
    for (int i = tid; i < B_ * DM_; i += 128) sh[i] = g_hn[i];
    __syncthreads();

    const int o = blockIdx.x * 128 + tid;
    float a0 = 0.f, a1 = 0.f, a2 = 0.f, a3 = 0.f;
    const float4* w4 = (const float4*)(ow + (size_t)o * DM_);
#pragma unroll 4
    for (int m4 = 0; m4 < DM_ / 4; m4++) {
        const float4 w = w4[m4];
        const int m = m4 * 4;
        a0 += sh[0 * DM_ + m] * w.x + sh[0 * DM_ + m + 1] * w.y + sh[0 * DM_ + m + 2] * w.z + sh[0 * DM_ + m + 3] * w.w;
        a1 += sh[1 * DM_ + m] * w.x + sh[1 * DM_ + m + 1] * w.y + sh[1 * DM_ + m + 2] * w.z + sh[1 * DM_ + m + 3] * w.w;
        a2 += sh[2 * DM_ + m] * w.x + sh[2 * DM_ + m + 1] * w.y + sh[2 * DM_ + m + 2] * w.z + sh[2 * DM_ + m + 3] * w.w;
        a3 += sh[3 * DM_ + m] * w.x + sh[3 * DM_ + m + 1] * w.y + sh[3 * DM_ + m + 2] * w.z + sh[3 * DM_ + m + 3] * w.w;
    }
    const float bo = ob[o];
    out[0 * IN_DIM_ + o] = a0 + bo;
    out[1 * IN_DIM_ + o] = a1 + bo;
    out[2 * IN_DIM_ + o] = a2 + bo;
    out[3 * IN_DIM_ + o] = a3 + bo;
}

// ---------------------------------------------------------------------------
extern "C" void kernel_launch(void* const* d_in, const int* in_sizes, int n_in,
                              void* d_out, int out_size)
{
    const float* x       = (const float*)d_in[0];
    const float* in_w    = (const float*)d_in[1];
    const float* in_b    = (const float*)d_in[2];
    const float* ln_g    = (const float*)d_in[3];
    const float* ln_b    = (const float*)d_in[4];
    const float* out_w   = (const float*)d_in[5];
    const float* out_b   = (const float*)d_in[6];
    const float* m_in_w  = (const float*)d_in[7];
    const float* conv_w  = (const float*)d_in[8];
    const float* conv_b  = (const float*)d_in[9];
    const float* xproj_w = (const float*)d_in[10];
    const float* dt_w    = (const float*)d_in[11];
    const float* dt_b    = (const float*)d_in[12];
    const float* A_log   = (const float*)d_in[13];
    const float* D_p     = (const float*)d_in[14];
    const float* m_out_w = (const float*)d_in[15];
    float* outp = (float*)d_out;

    float *ph, *pxz, *pxc, *pxdbl, *py, *ppart;
    cudaGetSymbolAddress((void**)&ph,    g_h);
    cudaGetSymbolAddress((void**)&pxz,   g_xz);
    cudaGetSymbolAddress((void**)&pxc,   g_xc);
    cudaGetSymbolAddress((void**)&pxdbl, g_xdbl);
    cudaGetSymbolAddress((void**)&py,    g_y);
    cudaGetSymbolAddress((void**)&ppart, g_part);

    // h = x @ in_w^T + in_b   (M=1024, N=512, K=16384, 16-way K-split)
    sgemm_atb<<<dim3(DM_ / 128, T_ / 128, 16), 256>>>(x, in_w, ppart, T_, DM_, IN_DIM_, IN_DIM_ / 16);
    reduce_kernel<<<(T_ * DM_ + 255) / 256, 256>>>(ppart, ph, T_ * DM_, 16, in_b, DM_);

    for (int i = 0; i < DEPTH_; i++) {
        // xz = h @ m_in_w[i]^T   (M=1024, N=2048, K=512) -> direct write
        sgemm_atb<<<dim3(2 * DI_ / 128, T_ / 128, 1), 256>>>(
            ph, m_in_w + (size_t)i * 2 * DI_ * DM_, pxz, T_, 2 * DI_, DM_, DM_);

        // causal conv + silu
        conv_silu_kernel<<<T_ * DI_ / 256, 256>>>(conv_w + i * DI_ * DC_, conv_b + i * DI_);

        // xdbl = xc @ xproj_w[i]^T  (M=1024, N=64, K=1024, 8-way split)
        sgemm_atb<<<dim3(1, T_ / 128, 8), 256>>>(
            pxc, xproj_w + (size_t)i * XPD_ * DI_, ppart, T_, XPD_, DI_, DI_ / 8);
        reduce_kernel<<<(T_ * XPD_ + 255) / 256, 256>>>(ppart, pxdbl, T_ * XPD_, 8, nullptr, XPD_);

        // dt = softplus(xdbl[:, :32] @ dt_w^T + dt_b)
        dt_kernel<<<dim3(DI_ / 256, T_), 256>>>(dt_w + (size_t)i * DI_ * DR_, dt_b + i * DI_);

        // selective scan + gating -> g_y
        scan_kernel<<<(B_ * DI_ * DS_) / 256, 256>>>(A_log + (size_t)i * DI_ * DS_, D_p + i * DI_);

        // h = y @ m_out_w[i]^T   (M=1024, N=512, K=1024, 4-way split)
        sgemm_atb<<<dim3(DM_ / 128, T_ / 128, 4), 256>>>(
            py, m_out_w + (size_t)i * DM_ * DI_, ppart, T_, DM_, DI_, DI_ / 4);
        reduce_kernel<<<(T_ * DM_ + 255) / 256, 256>>>(ppart, ph, T_ * DM_, 4, nullptr, DM_);
    }

    // final layernorm on last token + output projection
    ln_kernel<<<B_, 128>>>(ln_g, ln_b);
    outproj_kernel<<<IN_DIM_ / 128, 128>>>(out_w, out_b, outp);
}

// round 6
// speedup vs baseline: 1.0010x; 1.0010x over previous
#include <cuda_runtime.h>
#include <math.h>
#include <stdint.h>

// ---------------------------------------------------------------------------
// TemporalMamba: x -> in_proj -> 4x Mamba blocks -> LN(last token) -> out_proj
// All fp32. GEMMs: 128x128x8 register-blocked SGEMM with deterministic K-split
// (partials + reduce), scan: 16 lanes per (batch, channel) with shfl reduce.
// ---------------------------------------------------------------------------

#define IN_DIM_ 16384
#define DM_     512
#define DEPTH_  4
#define DI_     1024
#define DS_     16
#define DC_     4
#define DR_     32
#define B_      4
#define L_      256
#define T_      (B_ * L_)          // 1024 tokens
#define XPD_    (DR_ + 2 * DS_)    // 64

// Scratch (device globals: no allocation allowed)
__device__ float g_h[T_ * DM_];            // hidden  [1024, 512]
__device__ float g_xz[T_ * 2 * DI_];       // in-proj of block [1024, 2048]
__device__ float g_xc[T_ * DI_];           // conv+silu output [1024, 1024]
__device__ float g_xdbl[T_ * XPD_];        // x-proj [1024, 64]
__device__ float g_dt[T_ * DI_];           // softplus(dt) [1024, 1024]
__device__ float g_y[T_ * DI_];            // scan output [1024, 1024]
__device__ float g_hn[B_ * DM_];           // layernormed last tokens [4, 512]
__device__ float g_part[16 * T_ * DM_];    // K-split partials (max 16 x 1024 x 512)

// ---------------------------------------------------------------------------
// Generic C = A * W^T  (A: [M,K] row-major, W: [N,K] row-major).
// Block tile 128x128, BK=8, 256 threads, 8x8 per-thread microtile,
// single-stage smem with global prefetch. gridDim.z = K-split; each z writes
// its partial tile to C + z*M*N (deterministic; reduced by reduce_kernel).
// ---------------------------------------------------------------------------
__global__ __launch_bounds__(256) void sgemm_atb(
    const float* __restrict__ A, const float* __restrict__ W,
    float* __restrict__ C, int M, int N, int K, int kchunk)
{
    __shared__ float As[8][128];
    __shared__ float Bs[8][128];

    const int tid = threadIdx.x;
    const int tx  = tid & 15;
    const int ty  = tid >> 4;
    const int m0  = blockIdx.y * 128;
    const int n0  = blockIdx.x * 128;
    const int k0  = blockIdx.z * kchunk;
    const int k1  = min(K, k0 + kchunk);

    const int  lrow  = tid >> 1;          // 0..127
    const int  lk    = (tid & 1) * 4;     // 0 or 4
    const bool wv_ok = (n0 + lrow) < N;
    const float* Ap  = A + (size_t)(m0 + lrow) * K + lk;
    const float* Wp  = W + (size_t)(n0 + lrow) * K + lk;

    float acc[8][8];
#pragma unroll
    for (int i = 0; i < 8; i++)
#pragma unroll
        for (int j = 0; j < 8; j++) acc[i][j] = 0.f;

    float4 av = *(const float4*)(Ap + k0);
    float4 wv = wv_ok ? *(const float4*)(Wp + k0) : make_float4(0.f, 0.f, 0.f, 0.f);

    for (int k = k0; k < k1; k += 8) {
        __syncthreads();
        As[lk + 0][lrow] = av.x; As[lk + 1][lrow] = av.y;
        As[lk + 2][lrow] = av.z; As[lk + 3][lrow] = av.w;
        Bs[lk + 0][lrow] = wv.x; Bs[lk + 1][lrow] = wv.y;
        Bs[lk + 2][lrow] = wv.z; Bs[lk + 3][lrow] = wv.w;
        __syncthreads();

        if (k + 8 < k1) {   // prefetch next tile while computing this one
            av = *(const float4*)(Ap + k + 8);
            wv = wv_ok ? *(const float4*)(Wp + k + 8) : make_float4(0.f, 0.f, 0.f, 0.f);
        }

#pragma unroll
        for (int kk = 0; kk < 8; kk++) {
            float a[8], b[8];
            *(float4*)(a)     = *(const float4*)(&As[kk][ty * 8]);
            *(float4*)(a + 4) = *(const float4*)(&As[kk][ty * 8 + 4]);
            *(float4*)(b)     = *(const float4*)(&Bs[kk][tx * 8]);
            *(float4*)(b + 4) = *(const float4*)(&Bs[kk][tx * 8 + 4]);
#pragma unroll
            for (int i = 0; i < 8; i++)
#pragma unroll
                for (int j = 0; j < 8; j++)
                    acc[i][j] += a[i] * b[j];
        }
    }

    float* Cp = C + (size_t)blockIdx.z * M * N;
#pragma unroll
    for (int i = 0; i < 8; i++) {
        const int row = m0 + ty * 8 + i;
#pragma unroll
        for (int j = 0; j < 8; j += 4) {
            const int col = n0 + tx * 8 + j;
            if (col < N) {
                *(float4*)(&Cp[(size_t)row * N + col]) =
                    make_float4(acc[i][j], acc[i][j + 1], acc[i][j + 2], acc[i][j + 3]);
            }
        }
    }
}

// Sum ks partials (deterministic order) + optional per-column bias.
__global__ void reduce_kernel(const float* __restrict__ P, float* __restrict__ C,
                              int MN, int ks, const float* __restrict__ bias, int N)
{
    const int i = blockIdx.x * 256 + threadIdx.x;
    if (i >= MN) return;
    float s = 0.f;
    for (int z = 0; z < ks; z++) s += P[(size_t)z * MN + i];
    if (bias) s += bias[i % N];
    C[i] = s;
}

// Causal depthwise conv (width 4) + SiLU on xc = g_xz[:, :DI]
__global__ void conv_silu_kernel(const float* __restrict__ cw, const float* __restrict__ cb)
{
    const int idx = blockIdx.x * 256 + threadIdx.x;   // T_*DI_ threads
    const int c = idx & (DI_ - 1);
    const int t = idx >> 10;
    const int b = t >> 8;
    const int l = t & (L_ - 1);
    float acc = cb[c];
#pragma unroll
    for (int k = 0; k < DC_; k++) {
        const int ls = l - (DC_ - 1) + k;
        if (ls >= 0)
            acc += g_xz[(size_t)((b << 8) + ls) * (2 * DI_) + c] * cw[c * DC_ + k];
    }
    g_xc[idx] = acc / (1.f + expf(-acc));   // silu
}

// dt[t,d] = softplus( xdbl[t, :32] . dt_w[d, :] + dt_b[d] )
__global__ void dt_kernel(const float* __restrict__ dw, const float* __restrict__ db)
{
    __shared__ float sx[DR_];
    const int t = blockIdx.y;
    const int d = blockIdx.x * 256 + threadIdx.x;
    if (threadIdx.x < DR_) sx[threadIdx.x] = g_xdbl[t * XPD_ + threadIdx.x];
    __syncthreads();
    float acc = db[d];
    const float4* w4 = (const float4*)(dw + (size_t)d * DR_);
#pragma unroll
    for (int r = 0; r < DR_ / 4; r++) {
        const float4 w = w4[r];
        acc += sx[4 * r] * w.x + sx[4 * r + 1] * w.y +
               sx[4 * r + 2] * w.z + sx[4 * r + 3] * w.w;
    }
    const float sp = (acc > 20.f) ? acc : log1pf(expf(acc));
    g_dt[t * DI_ + d] = sp;
}

// Selective scan. 16 lanes per (b,d) pair: lane n owns state n (n<16).
// Per step: state = exp(dt*A_n)*state + (dt*xc)*B_n; y = sum_n state*C_n
// (4-round shfl-xor within the 16-lane group), epilogue y = (y + xc*D)*silu(z).
__global__ void scan_kernel(const float* __restrict__ Alog, const float* __restrict__ Dp)
{
    const int lane = threadIdx.x & 31;
    const int n    = lane & 15;
    const int p    = (((blockIdx.x * 256 + threadIdx.x) >> 5) << 1) + (lane >> 4);
    const int b    = p >> 10;           // / DI_
    const int d    = p & (DI_ - 1);

    const float A   = -expf(Alog[d * DS_ + n]);
    const float Dpd = Dp[d];
    float s = 0.f;

    for (int l = 0; l < L_; l++) {
        const int t = (b << 8) + l;
        const float dtv = g_dt[t * DI_ + d];
        const float xv  = g_xc[t * DI_ + d];
        const float q   = __expf(dtv * A);
        const float bm  = g_xdbl[t * XPD_ + DR_ + n];
        s = q * s + (dtv * xv) * bm;
        float v = s * g_xdbl[t * XPD_ + DR_ + DS_ + n];
        v += __shfl_xor_sync(0xFFFFFFFFu, v, 8);
        v += __shfl_xor_sync(0xFFFFFFFFu, v, 4);
        v += __shfl_xor_sync(0xFFFFFFFFu, v, 2);
        v += __shfl_xor_sync(0xFFFFFFFFu, v, 1);
        if (n == 0) {
            const float zv = g_xz[(size_t)t * (2 * DI_) + DI_ + d];
            const float yy = v + xv * Dpd;
            g_y[t * DI_ + d] = yy * (zv / (1.f + expf(-zv)));
        }
    }
}

// LayerNorm over last token of each batch
__global__ void ln_kernel(const float* __restrict__ gamma, const float* __restrict__ beta)
{
    __shared__ float red[128];
    const int b   = blockIdx.x;
    const int tid = threadIdx.x;   // 128
    const float* row = g_h + (size_t)((b + 1) * L_ - 1) * DM_;

    float v[4]; float s = 0.f;
#pragma unroll
    for (int i = 0; i < 4; i++) { v[i] = row[tid + i * 128]; s += v[i]; }
    red[tid] = s; __syncthreads();
    for (int o = 64; o > 0; o >>= 1) { if (tid < o) red[tid] += red[tid + o]; __syncthreads(); }
    const float mu = red[0] * (1.f / DM_);
    __syncthreads();

    float var = 0.f;
#pragma unroll
    for (int i = 0; i < 4; i++) { const float dd = v[i] - mu; var += dd * dd; }
    red[tid] = var; __syncthreads();
    for (int o = 64; o > 0; o >>= 1) { if (tid < o) red[tid] += red[tid + o]; __syncthreads(); }
    const float rstd = rsqrtf(red[0] * (1.f / DM_) + 1e-5f);

#pragma unroll
    for (int i = 0; i < 4; i++) {
        const int m = tid + i * 128;
        g_hn[b * DM_ + m] = (v[i] - mu) * rstd * gamma[m] + beta[m];
    }
}

// out[b, o] = hn[b,:] . out_w[o,:] + out_b[o]; one thread per o, all 4 batches
// share each out_w row read (32MB streamed once).
__global__ void outproj_kernel(const float* __restrict__ ow, const float* __restrict__ ob,
                               float* __restrict__ out)
{
    __shared__ float sh[B_ * DM_];
    const int tid = threadIdx.x;  // 128
    for (int i = tid; i < B_ * DM_; i += 128) sh[i] = g_hn[i];
    __syncthreads();

    const int o = blockIdx.x * 128 + tid;
    float a0 = 0.f, a1 = 0.f, a2 = 0.f, a3 = 0.f;
    const float4* w4 = (const float4*)(ow + (size_t)o * DM_);
#pragma unroll 4
    for (int m4 = 0; m4 < DM_ / 4; m4++) {
        const float4 w = w4[m4];
        const int m = m4 * 4;
        a0 += sh[0 * DM_ + m] * w.x + sh[0 * DM_ + m + 1] * w.y + sh[0 * DM_ + m + 2] * w.z + sh[0 * DM_ + m + 3] * w.w;
        a1 += sh[1 * DM_ + m] * w.x + sh[1 * DM_ + m + 1] * w.y + sh[1 * DM_ + m + 2] * w.z + sh[1 * DM_ + m + 3] * w.w;
        a2 += sh[2 * DM_ + m] * w.x + sh[2 * DM_ + m + 1] * w.y + sh[2 * DM_ + m + 2] * w.z + sh[2 * DM_ + m + 3] * w.w;
        a3 += sh[3 * DM_ + m] * w.x + sh[3 * DM_ + m + 1] * w.y + sh[3 * DM_ + m + 2] * w.z + sh[3 * DM_ + m + 3] * w.w;
    }
    const float bo = ob[o];
    out[0 * IN_DIM_ + o] = a0 + bo;
    out[1 * IN_DIM_ + o] = a1 + bo;
    out[2 * IN_DIM_ + o] = a2 + bo;
    out[3 * IN_DIM_ + o] = a3 + bo;
}

// ---------------------------------------------------------------------------
extern "C" void kernel_launch(void* const* d_in, const int* in_sizes, int n_in,
                              void* d_out, int out_size)
{
    const float* x       = (const float*)d_in[0];
    const float* in_w    = (const float*)d_in[1];
    const float* in_b    = (const float*)d_in[2];
    const float* ln_g    = (const float*)d_in[3];
    const float* ln_b    = (const float*)d_in[4];
    const float* out_w   = (const float*)d_in[5];
    const float* out_b   = (const float*)d_in[6];
    const float* m_in_w  = (const float*)d_in[7];
    const float* conv_w  = (const float*)d_in[8];
    const float* conv_b  = (const float*)d_in[9];
    const float* xproj_w = (const float*)d_in[10];
    const float* dt_w    = (const float*)d_in[11];
    const float* dt_b    = (const float*)d_in[12];
    const float* A_log   = (const float*)d_in[13];
    const float* D_p     = (const float*)d_in[14];
    const float* m_out_w = (const float*)d_in[15];
    float* outp = (float*)d_out;

    float *ph, *pxz, *pxc, *pxdbl, *py, *ppart;
    cudaGetSymbolAddress((void**)&ph,    g_h);
    cudaGetSymbolAddress((void**)&pxz,   g_xz);
    cudaGetSymbolAddress((void**)&pxc,   g_xc);
    cudaGetSymbolAddress((void**)&pxdbl, g_xdbl);
    cudaGetSymbolAddress((void**)&py,    g_y);
    cudaGetSymbolAddress((void**)&ppart, g_part);

    // h = x @ in_w^T + in_b   (M=1024, N=512, K=16384, 16-way K-split)
    sgemm_atb<<<dim3(DM_ / 128, T_ / 128, 16), 256>>>(x, in_w, ppart, T_, DM_, IN_DIM_, IN_DIM_ / 16);
    reduce_kernel<<<(T_ * DM_ + 255) / 256, 256>>>(ppart, ph, T_ * DM_, 16, in_b, DM_);

    for (int i = 0; i < DEPTH_; i++) {
        // xz = h @ m_in_w[i]^T   (M=1024, N=2048, K=512) -> direct write
        sgemm_atb<<<dim3(2 * DI_ / 128, T_ / 128, 1), 256>>>(
            ph, m_in_w + (size_t)i * 2 * DI_ * DM_, pxz, T_, 2 * DI_, DM_, DM_);

        // causal conv + silu
        conv_silu_kernel<<<T_ * DI_ / 256, 256>>>(conv_w + i * DI_ * DC_, conv_b + i * DI_);

        // xdbl = xc @ xproj_w[i]^T  (M=1024, N=64, K=1024, 8-way split)
        sgemm_atb<<<dim3(1, T_ / 128, 8), 256>>>(
            pxc, xproj_w + (size_t)i * XPD_ * DI_, ppart, T_, XPD_, DI_, DI_ / 8);
        reduce_kernel<<<(T_ * XPD_ + 255) / 256, 256>>>(ppart, pxdbl, T_ * XPD_, 8, nullptr, XPD_);

        // dt = softplus(xdbl[:, :32] @ dt_w^T + dt_b)
        dt_kernel<<<dim3(DI_ / 256, T_), 256>>>(dt_w + (size_t)i * DI_ * DR_, dt_b + i * DI_);

        // selective scan + gating -> g_y
        scan_kernel<<<(B_ * DI_ * DS_) / 256, 256>>>(A_log + (size_t)i * DI_ * DS_, D_p + i * DI_);

        // h = y @ m_out_w[i]^T   (M=1024, N=512, K=1024, 4-way split)
        sgemm_atb<<<dim3(DM_ / 128, T_ / 128, 4), 256>>>(
            py, m_out_w + (size_t)i * DM_ * DI_, ppart, T_, DM_, DI_, DI_ / 4);
        reduce_kernel<<<(T_ * DM_ + 255) / 256, 256>>>(ppart, ph, T_ * DM_, 4, nullptr, DM_);
    }

    // final layernorm on last token + output projection
    ln_kernel<<<B_, 128>>>(ln_g, ln_b);
    outproj_kernel<<<IN_DIM_ / 128, 128>>>(out_w, out_b, outp);
}

// round 10
// speedup vs baseline: 1.4832x; 1.4817x over previous
#include <cuda_runtime.h>
#include <cuda_bf16.h>
#include <math.h>
#include <stdint.h>

// ---------------------------------------------------------------------------
// TemporalMamba on GB300 (compute_103-safe): bf16 3-pass (hi/lo split) GEMMs
// on the tensor cores via mma.sync.m16n8k16 + ldmatrix, fp32 accumulation.
// Scalar conv/dt/scan/LN kernels proven in R6.
// ---------------------------------------------------------------------------

#define IN_DIM_ 16384
#define DM_     512
#define DEPTH_  4
#define DI_     1024
#define DS_     16
#define DC_     4
#define DR_     32
#define B_      4
#define L_      256
#define T_      (B_ * L_)          // 1024 tokens
#define XPD_    (DR_ + 2 * DS_)    // 64

// Scratch (device globals: no allocation allowed)
__device__ __align__(128) float g_h[T_ * DM_];
__device__ __align__(128) float g_xz[T_ * 2 * DI_];
__device__ __align__(128) float g_xc[T_ * DI_];
__device__ __align__(128) float g_xdbl[T_ * XPD_];
__device__ __align__(128) float g_dt[T_ * DI_];
__device__ __align__(128) float g_y[T_ * DI_];
__device__ __align__(128) float g_hn[B_ * DM_];
__device__ __align__(128) float g_part[8 * T_ * XPD_ > 4 * T_ * DM_ ?
                                       8 * T_ * XPD_ : 4 * T_ * DM_];

// ---------------------------------------------------------------------------
// Warp-MMA helpers (baseline PTX, legal on compute_103)
// ---------------------------------------------------------------------------
__device__ __forceinline__ uint32_t smem_u32(const void* p) {
    return (uint32_t)__cvta_generic_to_shared(p);
}

__device__ __forceinline__ void ldm4(uint32_t* r, uint32_t a) {
    asm volatile("ldmatrix.sync.aligned.m8n8.x4.shared.b16 {%0,%1,%2,%3}, [%4];"
                 : "=r"(r[0]), "=r"(r[1]), "=r"(r[2]), "=r"(r[3]) : "r"(a));
}

__device__ __forceinline__ void mma16816(float* c, const uint32_t* a, const uint32_t* b) {
    asm volatile("mma.sync.aligned.m16n8k16.row.col.f32.bf16.bf16.f32 "
                 "{%0,%1,%2,%3}, {%4,%5,%6,%7}, {%8,%9}, {%0,%1,%2,%3};"
                 : "+f"(c[0]), "+f"(c[1]), "+f"(c[2]), "+f"(c[3])
                 : "r"(a[0]), "r"(a[1]), "r"(a[2]), "r"(a[3]),
                   "r"(b[0]), "r"(b[1]));
}

// fp32x4 -> bf16 hi plane + bf16 lo plane (2-term split) at element offset off.
__device__ __forceinline__ void split4(__nv_bfloat16* h, __nv_bfloat16* l,
                                       int off, float4 f) {
    __nv_bfloat162 h0 = __floats2bfloat162_rn(f.x, f.y);
    __nv_bfloat162 h1 = __floats2bfloat162_rn(f.z, f.w);
    float rx = f.x - __bfloat162float(h0.x);
    float ry = f.y - __bfloat162float(h0.y);
    float rz = f.z - __bfloat162float(h1.x);
    float rw = f.w - __bfloat162float(h1.y);
    __nv_bfloat162 l0 = __floats2bfloat162_rn(rx, ry);
    __nv_bfloat162 l1 = __floats2bfloat162_rn(rz, rw);
    *(__nv_bfloat162*)(h + off)     = h0;
    *(__nv_bfloat162*)(h + off + 2) = h1;
    *(__nv_bfloat162*)(l + off)     = l0;
    *(__nv_bfloat162*)(l + off + 2) = l1;
}

// ---------------------------------------------------------------------------
// Tensor-core GEMM (HMMA): C(z-slab) = A[M,K] * W[N,K]^T, fp32 I/O.
// CTA: 128 x NT output tile, 256 threads = 8 warps (4m x 2n), BK=32,
// 3-pass hi/lo bf16 split with fp32 mma accumulators, register prefetch.
// Requires: M%128==0, N%NT==0, kchunk%32==0.
// ---------------------------------------------------------------------------
template<int NT>
__global__ __launch_bounds__(256) void hgemm(
    const float* __restrict__ A, const float* __restrict__ W,
    float* __restrict__ C, int M, int N, int K, int kchunk)
{
    constexpr int RP  = 40;        // padded row length (bf16 elems) -> 80B
    constexpr int NFR = NT / 16;   // n8-frags per warp (8 or 4)
    constexpr int WI  = NT / 32;   // W-tile float4 iters per thread (4 or 2)

    __shared__ __align__(128) __nv_bfloat16 sAh[128 * RP];
    __shared__ __align__(128) __nv_bfloat16 sAl[128 * RP];
    __shared__ __align__(128) __nv_bfloat16 sWh[NT * RP];
    __shared__ __align__(128) __nv_bfloat16 sWl[NT * RP];

    const int tid  = threadIdx.x;
    const int wid  = tid >> 5;
    const int lane = tid & 31;
    const int wm   = wid & 3;       // m-slice (32 rows each)
    const int wn   = wid >> 2;      // n-slice (NT/2 cols each)
    const int m0   = blockIdx.y * 128;
    const int n0   = blockIdx.x * NT;
    const int k0   = blockIdx.z * kchunk;
    const int nch  = kchunk >> 5;

    float acc[2][NFR][4];
#pragma unroll
    for (int mi = 0; mi < 2; mi++)
#pragma unroll
        for (int ni = 0; ni < NFR; ni++)
#pragma unroll
            for (int j = 0; j < 4; j++) acc[mi][ni][j] = 0.f;

    float4 pa[4], pw[WI];

    // initial prefetch (chunk 0)
#pragma unroll
    for (int i = 0; i < 4; i++) {
        const int idx = i * 256 + tid;
        pa[i] = *(const float4*)(A + (size_t)(m0 + (idx >> 3)) * K + k0 + (idx & 7) * 4);
    }
#pragma unroll
    for (int i = 0; i < WI; i++) {
        const int idx = i * 256 + tid;
        pw[i] = *(const float4*)(W + (size_t)(n0 + (idx >> 3)) * K + k0 + (idx & 7) * 4);
    }

    const uint32_t uAh = smem_u32(sAh), uAl = smem_u32(sAl);
    const uint32_t uWh = smem_u32(sWh), uWl = smem_u32(sWl);

    for (int c = 0; c < nch; c++) {
        __syncthreads();   // previous chunk's mma reads done
#pragma unroll
        for (int i = 0; i < 4; i++) {
            const int idx = i * 256 + tid;
            split4(sAh, sAl, (idx >> 3) * RP + (idx & 7) * 4, pa[i]);
        }
#pragma unroll
        for (int i = 0; i < WI; i++) {
            const int idx = i * 256 + tid;
            split4(sWh, sWl, (idx >> 3) * RP + (idx & 7) * 4, pw[i]);
        }
        __syncthreads();

        if (c + 1 < nch) {
            const int kb = k0 + (c + 1) * 32;
#pragma unroll
            for (int i = 0; i < 4; i++) {
                const int idx = i * 256 + tid;
                pa[i] = *(const float4*)(A + (size_t)(m0 + (idx >> 3)) * K + kb + (idx & 7) * 4);
            }
#pragma unroll
            for (int i = 0; i < WI; i++) {
                const int idx = i * 256 + tid;
                pw[i] = *(const float4*)(W + (size_t)(n0 + (idx >> 3)) * K + kb + (idx & 7) * 4);
            }
        }

        // 3 passes: (Ah,Wh), (Al,Wh), (Ah,Wl)
#pragma unroll
        for (int p = 0; p < 3; p++) {
            const uint32_t ab = (p == 1) ? uAl : uAh;
            const uint32_t bb = (p == 2) ? uWl : uWh;
#pragma unroll
            for (int ks = 0; ks < 2; ks++) {
                uint32_t af[2][4];
#pragma unroll
                for (int mi = 0; mi < 2; mi++) {
                    const int row = wm * 32 + mi * 16 + ((lane >> 3) & 1) * 8 + (lane & 7);
                    const int col = ks * 16 + (lane >> 4) * 8;
                    ldm4(af[mi], ab + (uint32_t)(row * RP + col) * 2);
                }
                uint32_t bfv[NFR][2];
#pragma unroll
                for (int np = 0; np < NFR / 2; np++) {
                    const int row = wn * (NT / 2) + np * 16 + (lane >> 4) * 8 + (lane & 7);
                    const int col = ks * 16 + ((lane >> 3) & 1) * 8;
                    uint32_t r[4];
                    ldm4(r, bb + (uint32_t)(row * RP + col) * 2);
                    bfv[2 * np][0] = r[0]; bfv[2 * np][1] = r[1];
                    bfv[2 * np + 1][0] = r[2]; bfv[2 * np + 1][1] = r[3];
                }
#pragma unroll
                for (int mi = 0; mi < 2; mi++)
#pragma unroll
                    for (int ni = 0; ni < NFR; ni++)
                        mma16816(acc[mi][ni], af[mi], bfv[ni]);
            }
        }
    }

    // Epilogue: fragment layout direct to global (8B stores)
    float* Cp = C + (size_t)blockIdx.z * M * N;
    const int gid = lane >> 2, tig = lane & 3;
#pragma unroll
    for (int mi = 0; mi < 2; mi++) {
#pragma unroll
        for (int ni = 0; ni < NFR; ni++) {
            const int r  = m0 + wm * 32 + mi * 16 + gid;
            const int cc = n0 + wn * (NT / 2) + ni * 8 + tig * 2;
            float2 v0 = make_float2(acc[mi][ni][0], acc[mi][ni][1]);
            float2 v1 = make_float2(acc[mi][ni][2], acc[mi][ni][3]);
            *(float2*)&Cp[(size_t)r * N + cc]       = v0;
            *(float2*)&Cp[(size_t)(r + 8) * N + cc] = v1;
        }
    }
}

// ---------------------------------------------------------------------------
// Elementwise / scan / LN kernels (proven in R6)
// ---------------------------------------------------------------------------
__global__ void reduce_kernel(const float* __restrict__ P, float* __restrict__ C,
                              int MN, int ks, const float* __restrict__ bias, int N)
{
    const int i = blockIdx.x * 256 + threadIdx.x;
    if (i >= MN) return;
    float s = 0.f;
    for (int z = 0; z < ks; z++) s += P[(size_t)z * MN + i];
    if (bias) s += bias[i % N];
    C[i] = s;
}

__global__ void conv_silu_kernel(const float* __restrict__ cw, const float* __restrict__ cb)
{
    const int idx = blockIdx.x * 256 + threadIdx.x;   // T_*DI_ threads
    const int c = idx & (DI_ - 1);
    const int t = idx >> 10;
    const int b = t >> 8;
    const int l = t & (L_ - 1);
    float acc = cb[c];
#pragma unroll
    for (int k = 0; k < DC_; k++) {
        const int ls = l - (DC_ - 1) + k;
        if (ls >= 0)
            acc += g_xz[(size_t)((b << 8) + ls) * (2 * DI_) + c] * cw[c * DC_ + k];
    }
    g_xc[idx] = acc / (1.f + __expf(-acc));
}

__global__ void dt_kernel(const float* __restrict__ dw, const float* __restrict__ db)
{
    __shared__ float sx[DR_];
    const int t = blockIdx.y;
    const int d = blockIdx.x * 256 + threadIdx.x;
    if (threadIdx.x < DR_) sx[threadIdx.x] = g_xdbl[t * XPD_ + threadIdx.x];
    __syncthreads();
    float acc = db[d];
    const float4* w4 = (const float4*)(dw + (size_t)d * DR_);
#pragma unroll
    for (int r = 0; r < DR_ / 4; r++) {
        const float4 w = w4[r];
        acc += sx[4 * r] * w.x + sx[4 * r + 1] * w.y +
               sx[4 * r + 2] * w.z + sx[4 * r + 3] * w.w;
    }
    const float sp = (acc > 20.f) ? acc : log1pf(__expf(acc));
    g_dt[t * DI_ + d] = sp;
}

__global__ void scan_kernel(const float* __restrict__ Alog, const float* __restrict__ Dp)
{
    const int lane = threadIdx.x & 31;
    const int n    = lane & 15;
    const int p    = (((blockIdx.x * 256 + threadIdx.x) >> 5) << 1) + (lane >> 4);
    const int b    = p >> 10;
    const int d    = p & (DI_ - 1);

    const float A   = -__expf(Alog[d * DS_ + n]);
    const float Dpd = Dp[d];
    float s = 0.f;

    for (int l = 0; l < L_; l++) {
        const int t = (b << 8) + l;
        const float dtv = g_dt[t * DI_ + d];
        const float xv  = g_xc[t * DI_ + d];
        const float q   = __expf(dtv * A);
        const float bm  = g_xdbl[t * XPD_ + DR_ + n];
        s = q * s + (dtv * xv) * bm;
        float v = s * g_xdbl[t * XPD_ + DR_ + DS_ + n];
        v += __shfl_xor_sync(0xFFFFFFFFu, v, 8);
        v += __shfl_xor_sync(0xFFFFFFFFu, v, 4);
        v += __shfl_xor_sync(0xFFFFFFFFu, v, 2);
        v += __shfl_xor_sync(0xFFFFFFFFu, v, 1);
        if (n == 0) {
            const float zv = g_xz[(size_t)t * (2 * DI_) + DI_ + d];
            const float yy = v + xv * Dpd;
            g_y[t * DI_ + d] = yy * (zv / (1.f + __expf(-zv)));
        }
    }
}

__global__ void ln_kernel(const float* __restrict__ gamma, const float* __restrict__ beta)
{
    __shared__ float red[128];
    const int b   = blockIdx.x;
    const int tid = threadIdx.x;   // 128
    const float* row = g_h + (size_t)((b + 1) * L_ - 1) * DM_;

    float v[4]; float s = 0.f;
#pragma unroll
    for (int i = 0; i < 4; i++) { v[i] = row[tid + i * 128]; s += v[i]; }
    red[tid] = s; __syncthreads();
    for (int o = 64; o > 0; o >>= 1) { if (tid < o) red[tid] += red[tid + o]; __syncthreads(); }
    const float mu = red[0] * (1.f / DM_);
    __syncthreads();

    float var = 0.f;
#pragma unroll
    for (int i = 0; i < 4; i++) { const float dd = v[i] - mu; var += dd * dd; }
    red[tid] = var; __syncthreads();
    for (int o = 64; o > 0; o >>= 1) { if (tid < o) red[tid] += red[tid + o]; __syncthreads(); }
    const float rstd = rsqrtf(red[0] * (1.f / DM_) + 1e-5f);

#pragma unroll
    for (int i = 0; i < 4; i++) {
        const int m = tid + i * 128;
        g_hn[b * DM_ + m] = (v[i] - mu) * rstd * gamma[m] + beta[m];
    }
}

__global__ void outproj_kernel(const float* __restrict__ ow, const float* __restrict__ ob,
                               float* __restrict__ out)
{
    __shared__ float sh[B_ * DM_];
    const int tid = threadIdx.x;  // 128
    for (int i = tid; i < B_ * DM_; i += 128) sh[i] = g_hn[i];
    __syncthreads();

    const int o = blockIdx.x * 128 + tid;
    float a0 = 0.f, a1 = 0.f, a2 = 0.f, a3 = 0.f;
    const float4* w4 = (const float4*)(ow + (size_t)o * DM_);
#pragma unroll 4
    for (int m4 = 0; m4 < DM_ / 4; m4++) {
        const float4 w = w4[m4];
        const int m = m4 * 4;
        a0 += sh[0 * DM_ + m] * w.x + sh[0 * DM_ + m + 1] * w.y + sh[0 * DM_ + m + 2] * w.z + sh[0 * DM_ + m + 3] * w.w;
        a1 += sh[1 * DM_ + m] * w.x + sh[1 * DM_ + m + 1] * w.y + sh[1 * DM_ + m + 2] * w.z + sh[1 * DM_ + m + 3] * w.w;
        a2 += sh[2 * DM_ + m] * w.x + sh[2 * DM_ + m + 1] * w.y + sh[2 * DM_ + m + 2] * w.z + sh[2 * DM_ + m + 3] * w.w;
        a3 += sh[3 * DM_ + m] * w.x + sh[3 * DM_ + m + 1] * w.y + sh[3 * DM_ + m + 2] * w.z + sh[3 * DM_ + m + 3] * w.w;
    }
    const float bo = ob[o];
    out[0 * IN_DIM_ + o] = a0 + bo;
    out[1 * IN_DIM_ + o] = a1 + bo;
    out[2 * IN_DIM_ + o] = a2 + bo;
    out[3 * IN_DIM_ + o] = a3 + bo;
}

// ---------------------------------------------------------------------------
extern "C" void kernel_launch(void* const* d_in, const int* in_sizes, int n_in,
                              void* d_out, int out_size)
{
    const float* x       = (const float*)d_in[0];
    const float* in_w    = (const float*)d_in[1];
    const float* in_b    = (const float*)d_in[2];
    const float* ln_g    = (const float*)d_in[3];
    const float* ln_b    = (const float*)d_in[4];
    const float* out_w   = (const float*)d_in[5];
    const float* out_b   = (const float*)d_in[6];
    const float* m_in_w  = (const float*)d_in[7];
    const float* conv_w  = (const float*)d_in[8];
    const float* conv_b  = (const float*)d_in[9];
    const float* xproj_w = (const float*)d_in[10];
    const float* dt_w    = (const float*)d_in[11];
    const float* dt_b    = (const float*)d_in[12];
    const float* A_log   = (const float*)d_in[13];
    const float* D_p     = (const float*)d_in[14];
    const float* m_out_w = (const float*)d_in[15];
    float* outp = (float*)d_out;

    float *ph, *pxz, *pxc, *pxdbl, *py, *ppart;
    cudaGetSymbolAddress((void**)&ph,    g_h);
    cudaGetSymbolAddress((void**)&pxz,   g_xz);
    cudaGetSymbolAddress((void**)&pxc,   g_xc);
    cudaGetSymbolAddress((void**)&pxdbl, g_xdbl);
    cudaGetSymbolAddress((void**)&py,    g_y);
    cudaGetSymbolAddress((void**)&ppart, g_part);

    // h = x @ in_w^T + in_b   (M=1024, N=512, K=16384, K-split 4 -> 128 CTAs)
    hgemm<128><<<dim3(DM_ / 128, T_ / 128, 4), 256>>>(
        x, in_w, ppart, T_, DM_, IN_DIM_, IN_DIM_ / 4);
    reduce_kernel<<<(T_ * DM_ + 255) / 256, 256>>>(ppart, ph, T_ * DM_, 4, in_b, DM_);

    for (int i = 0; i < DEPTH_; i++) {
        // xz = h @ m_in_w[i]^T   (M=1024, N=2048, K=512) -> 128 CTAs, direct
        hgemm<128><<<dim3(2 * DI_ / 128, T_ / 128, 1), 256>>>(
            ph, m_in_w + (size_t)i * 2 * DI_ * DM_, pxz, T_, 2 * DI_, DM_, DM_);

        // causal conv + silu
        conv_silu_kernel<<<T_ * DI_ / 256, 256>>>(conv_w + i * DI_ * DC_, conv_b + i * DI_);

        // xdbl = xc @ xproj_w[i]^T  (M=1024, N=64, K=1024, K-split 8 -> 64 CTAs)
        hgemm<64><<<dim3(1, T_ / 128, 8), 256>>>(
            pxc, xproj_w + (size_t)i * XPD_ * DI_, ppart, T_, XPD_, DI_, DI_ / 8);
        reduce_kernel<<<(T_ * XPD_ + 255) / 256, 256>>>(ppart, pxdbl, T_ * XPD_, 8, nullptr, XPD_);

        // dt = softplus(xdbl[:, :32] @ dt_w^T + dt_b)
        dt_kernel<<<dim3(DI_ / 256, T_), 256>>>(dt_w + (size_t)i * DI_ * DR_, dt_b + i * DI_);

        // selective scan + gating -> g_y
        scan_kernel<<<(B_ * DI_ * DS_) / 256, 256>>>(A_log + (size_t)i * DI_ * DS_, D_p + i * DI_);

        // h = y @ m_out_w[i]^T   (M=1024, N=512, K=1024, K-split 4 -> 128 CTAs)
        hgemm<128><<<dim3(DM_ / 128, T_ / 128, 4), 256>>>(
            py, m_out_w + (size_t)i * DM_ * DI_, ppart, T_, DM_, DI_, DI_ / 4);
        reduce_kernel<<<(T_ * DM_ + 255) / 256, 256>>>(ppart, ph, T_ * DM_, 4, nullptr, DM_);
    }

    // final layernorm on last token + output projection
    ln_kernel<<<B_, 128>>>(ln_g, ln_b);
    outproj_kernel<<<IN_DIM_ / 128, 128>>>(out_w, out_b, outp);
}

// round 11
// speedup vs baseline: 1.4840x; 1.0006x over previous
#include <cuda_runtime.h>
#include <cuda_bf16.h>
#include <math.h>
#include <stdint.h>

// ---------------------------------------------------------------------------
// TemporalMamba on GB300 (compute_103-safe): bf16 3-pass (hi/lo split) GEMMs
// via mma.sync.m16n8k16 + ldmatrix, fp32 accumulation.
// R11: NT=64 tiles, 2 CTAs/SM occupancy, 256-CTA grids, Bh register caching.
// ---------------------------------------------------------------------------

#define IN_DIM_ 16384
#define DM_     512
#define DEPTH_  4
#define DI_     1024
#define DS_     16
#define DC_     4
#define DR_     32
#define B_      4
#define L_      256
#define T_      (B_ * L_)          // 1024 tokens
#define XPD_    (DR_ + 2 * DS_)    // 64

// Scratch (device globals: no allocation allowed)
__device__ __align__(128) float g_h[T_ * DM_];
__device__ __align__(128) float g_xz[T_ * 2 * DI_];
__device__ __align__(128) float g_xc[T_ * DI_];
__device__ __align__(128) float g_xdbl[T_ * XPD_];
__device__ __align__(128) float g_dt[T_ * DI_];
__device__ __align__(128) float g_y[T_ * DI_];
__device__ __align__(128) float g_hn[B_ * DM_];
__device__ __align__(128) float g_part[16 * T_ * XPD_ > 4 * T_ * DM_ ?
                                       16 * T_ * XPD_ : 4 * T_ * DM_];

// ---------------------------------------------------------------------------
// Warp-MMA helpers (baseline PTX, legal on compute_103)
// ---------------------------------------------------------------------------
__device__ __forceinline__ uint32_t smem_u32(const void* p) {
    return (uint32_t)__cvta_generic_to_shared(p);
}

__device__ __forceinline__ void ldm4(uint32_t* r, uint32_t a) {
    asm volatile("ldmatrix.sync.aligned.m8n8.x4.shared.b16 {%0,%1,%2,%3}, [%4];"
                 : "=r"(r[0]), "=r"(r[1]), "=r"(r[2]), "=r"(r[3]) : "r"(a));
}

__device__ __forceinline__ void mma16816(float* c, const uint32_t* a, const uint32_t* b) {
    asm volatile("mma.sync.aligned.m16n8k16.row.col.f32.bf16.bf16.f32 "
                 "{%0,%1,%2,%3}, {%4,%5,%6,%7}, {%8,%9}, {%0,%1,%2,%3};"
                 : "+f"(c[0]), "+f"(c[1]), "+f"(c[2]), "+f"(c[3])
                 : "r"(a[0]), "r"(a[1]), "r"(a[2]), "r"(a[3]),
                   "r"(b[0]), "r"(b[1]));
}

// fp32x4 -> bf16 hi plane + bf16 lo plane (2-term split) at element offset off.
__device__ __forceinline__ void split4(__nv_bfloat16* h, __nv_bfloat16* l,
                                       int off, float4 f) {
    __nv_bfloat162 h0 = __floats2bfloat162_rn(f.x, f.y);
    __nv_bfloat162 h1 = __floats2bfloat162_rn(f.z, f.w);
    float rx = f.x - __bfloat162float(h0.x);
    float ry = f.y - __bfloat162float(h0.y);
    float rz = f.z - __bfloat162float(h1.x);
    float rw = f.w - __bfloat162float(h1.y);
    __nv_bfloat162 l0 = __floats2bfloat162_rn(rx, ry);
    __nv_bfloat162 l1 = __floats2bfloat162_rn(rz, rw);
    *(__nv_bfloat162*)(h + off)     = h0;
    *(__nv_bfloat162*)(h + off + 2) = h1;
    *(__nv_bfloat162*)(l + off)     = l0;
    *(__nv_bfloat162*)(l + off + 2) = l1;
}

// ---------------------------------------------------------------------------
// Tensor-core GEMM (HMMA): C(z-slab) = A[M,K] * W[N,K]^T, fp32 I/O.
// CTA: 128 x 64 output tile, 256 threads = 8 warps (4m x 2n, warp tile 32x32),
// BK=32, 3-pass hi/lo bf16 split, Bh fragments register-cached across passes.
// 30KB smem, <=128 regs -> 2 CTAs/SM. Requires M%128==0, N%64==0, kchunk%32==0.
// ---------------------------------------------------------------------------
__global__ __launch_bounds__(256, 2) void hgemm(
    const float* __restrict__ A, const float* __restrict__ W,
    float* __restrict__ C, int M, int N, int K, int kchunk)
{
    constexpr int NT  = 64;
    constexpr int RP  = 40;        // padded row length (bf16 elems) -> 80B
    constexpr int NFR = NT / 16;   // 4 n8-frags per warp

    __shared__ __align__(128) __nv_bfloat16 sAh[128 * RP];
    __shared__ __align__(128) __nv_bfloat16 sAl[128 * RP];
    __shared__ __align__(128) __nv_bfloat16 sWh[NT * RP];
    __shared__ __align__(128) __nv_bfloat16 sWl[NT * RP];

    const int tid  = threadIdx.x;
    const int wid  = tid >> 5;
    const int lane = tid & 31;
    const int wm   = wid & 3;       // m-slice (32 rows)
    const int wn   = wid >> 2;      // n-slice (32 cols)
    const int m0   = blockIdx.y * 128;
    const int n0   = blockIdx.x * NT;
    const int k0   = blockIdx.z * kchunk;
    const int nch  = kchunk >> 5;

    float acc[2][NFR][4];
#pragma unroll
    for (int mi = 0; mi < 2; mi++)
#pragma unroll
        for (int ni = 0; ni < NFR; ni++)
#pragma unroll
            for (int j = 0; j < 4; j++) acc[mi][ni][j] = 0.f;

    float4 pa[4], pw[2];

    // initial prefetch (chunk 0): A 128x32 fp32, W 64x32 fp32
#pragma unroll
    for (int i = 0; i < 4; i++) {
        const int idx = i * 256 + tid;
        pa[i] = *(const float4*)(A + (size_t)(m0 + (idx >> 3)) * K + k0 + (idx & 7) * 4);
    }
#pragma unroll
    for (int i = 0; i < 2; i++) {
        const int idx = i * 256 + tid;
        pw[i] = *(const float4*)(W + (size_t)(n0 + (idx >> 3)) * K + k0 + (idx & 7) * 4);
    }

    const uint32_t uAh = smem_u32(sAh), uAl = smem_u32(sAl);
    const uint32_t uWh = smem_u32(sWh), uWl = smem_u32(sWl);

    for (int c = 0; c < nch; c++) {
        __syncthreads();   // previous chunk's mma reads done
#pragma unroll
        for (int i = 0; i < 4; i++) {
            const int idx = i * 256 + tid;
            split4(sAh, sAl, (idx >> 3) * RP + (idx & 7) * 4, pa[i]);
        }
#pragma unroll
        for (int i = 0; i < 2; i++) {
            const int idx = i * 256 + tid;
            split4(sWh, sWl, (idx >> 3) * RP + (idx & 7) * 4, pw[i]);
        }
        __syncthreads();

        if (c + 1 < nch) {
            const int kb = k0 + (c + 1) * 32;
#pragma unroll
            for (int i = 0; i < 4; i++) {
                const int idx = i * 256 + tid;
                pa[i] = *(const float4*)(A + (size_t)(m0 + (idx >> 3)) * K + kb + (idx & 7) * 4);
            }
#pragma unroll
            for (int i = 0; i < 2; i++) {
                const int idx = i * 256 + tid;
                pw[i] = *(const float4*)(W + (size_t)(n0 + (idx >> 3)) * K + kb + (idx & 7) * 4);
            }
        }

        // ks-outer; Bh cached in regs across passes 0 (Ah) and 1 (Al).
#pragma unroll
        for (int ks = 0; ks < 2; ks++) {
            uint32_t bh[NFR][2], af[2][4];
            // load Bh (hi plane of W)
#pragma unroll
            for (int np = 0; np < NFR / 2; np++) {
                const int row = wn * (NT / 2) + np * 16 + (lane >> 4) * 8 + (lane & 7);
                const int col = ks * 16 + ((lane >> 3) & 1) * 8;
                uint32_t r[4];
                ldm4(r, uWh + (uint32_t)(row * RP + col) * 2);
                bh[2 * np][0] = r[0]; bh[2 * np][1] = r[1];
                bh[2 * np + 1][0] = r[2]; bh[2 * np + 1][1] = r[3];
            }
            // pass 0: Ah x Bh
#pragma unroll
            for (int mi = 0; mi < 2; mi++) {
                const int row = wm * 32 + mi * 16 + ((lane >> 3) & 1) * 8 + (lane & 7);
                const int col = ks * 16 + (lane >> 4) * 8;
                ldm4(af[mi], uAh + (uint32_t)(row * RP + col) * 2);
            }
#pragma unroll
            for (int mi = 0; mi < 2; mi++)
#pragma unroll
                for (int ni = 0; ni < NFR; ni++)
                    mma16816(acc[mi][ni], af[mi], bh[ni]);
            // pass 1: Al x Bh (Bh reused from regs)
#pragma unroll
            for (int mi = 0; mi < 2; mi++) {
                const int row = wm * 32 + mi * 16 + ((lane >> 3) & 1) * 8 + (lane & 7);
                const int col = ks * 16 + (lane >> 4) * 8;
                ldm4(af[mi], uAl + (uint32_t)(row * RP + col) * 2);
            }
#pragma unroll
            for (int mi = 0; mi < 2; mi++)
#pragma unroll
                for (int ni = 0; ni < NFR; ni++)
                    mma16816(acc[mi][ni], af[mi], bh[ni]);
            // pass 2: Ah x Bl (reload Ah; Bl overwrites bh regs)
#pragma unroll
            for (int np = 0; np < NFR / 2; np++) {
                const int row = wn * (NT / 2) + np * 16 + (lane >> 4) * 8 + (lane & 7);
                const int col = ks * 16 + ((lane >> 3) & 1) * 8;
                uint32_t r[4];
                ldm4(r, uWl + (uint32_t)(row * RP + col) * 2);
                bh[2 * np][0] = r[0]; bh[2 * np][1] = r[1];
                bh[2 * np + 1][0] = r[2]; bh[2 * np + 1][1] = r[3];
            }
#pragma unroll
            for (int mi = 0; mi < 2; mi++) {
                const int row = wm * 32 + mi * 16 + ((lane >> 3) & 1) * 8 + (lane & 7);
                const int col = ks * 16 + (lane >> 4) * 8;
                ldm4(af[mi], uAh + (uint32_t)(row * RP + col) * 2);
            }
#pragma unroll
            for (int mi = 0; mi < 2; mi++)
#pragma unroll
                for (int ni = 0; ni < NFR; ni++)
                    mma16816(acc[mi][ni], af[mi], bh[ni]);
        }
    }

    // Epilogue: fragment layout direct to global (8B stores)
    float* Cp = C + (size_t)blockIdx.z * M * N;
    const int gid = lane >> 2, tig = lane & 3;
#pragma unroll
    for (int mi = 0; mi < 2; mi++) {
#pragma unroll
        for (int ni = 0; ni < NFR; ni++) {
            const int r  = m0 + wm * 32 + mi * 16 + gid;
            const int cc = n0 + wn * (NT / 2) + ni * 8 + tig * 2;
            float2 v0 = make_float2(acc[mi][ni][0], acc[mi][ni][1]);
            float2 v1 = make_float2(acc[mi][ni][2], acc[mi][ni][3]);
            *(float2*)&Cp[(size_t)r * N + cc]       = v0;
            *(float2*)&Cp[(size_t)(r + 8) * N + cc] = v1;
        }
    }
}

// ---------------------------------------------------------------------------
// Elementwise / scan / LN kernels (proven in R6)
// ---------------------------------------------------------------------------
__global__ void reduce_kernel(const float* __restrict__ P, float* __restrict__ C,
                              int MN, int ks, const float* __restrict__ bias, int N)
{
    const int i = blockIdx.x * 256 + threadIdx.x;
    if (i >= MN) return;
    float s = 0.f;
    for (int z = 0; z < ks; z++) s += P[(size_t)z * MN + i];
    if (bias) s += bias[i % N];
    C[i] = s;
}

__global__ void conv_silu_kernel(const float* __restrict__ cw, const float* __restrict__ cb)
{
    const int idx = blockIdx.x * 256 + threadIdx.x;   // T_*DI_ threads
    const int c = idx & (DI_ - 1);
    const int t = idx >> 10;
    const int b = t >> 8;
    const int l = t & (L_ - 1);
    float acc = cb[c];
#pragma unroll
    for (int k = 0; k < DC_; k++) {
        const int ls = l - (DC_ - 1) + k;
        if (ls >= 0)
            acc += g_xz[(size_t)((b << 8) + ls) * (2 * DI_) + c] * cw[c * DC_ + k];
    }
    g_xc[idx] = acc / (1.f + __expf(-acc));
}

__global__ void dt_kernel(const float* __restrict__ dw, const float* __restrict__ db)
{
    __shared__ float sx[DR_];
    const int t = blockIdx.y;
    const int d = blockIdx.x * 256 + threadIdx.x;
    if (threadIdx.x < DR_) sx[threadIdx.x] = g_xdbl[t * XPD_ + threadIdx.x];
    __syncthreads();
    float acc = db[d];
    const float4* w4 = (const float4*)(dw + (size_t)d * DR_);
#pragma unroll
    for (int r = 0; r < DR_ / 4; r++) {
        const float4 w = w4[r];
        acc += sx[4 * r] * w.x + sx[4 * r + 1] * w.y +
               sx[4 * r + 2] * w.z + sx[4 * r + 3] * w.w;
    }
    const float sp = (acc > 20.f) ? acc : log1pf(__expf(acc));
    g_dt[t * DI_ + d] = sp;
}

__global__ void scan_kernel(const float* __restrict__ Alog, const float* __restrict__ Dp)
{
    const int lane = threadIdx.x & 31;
    const int n    = lane & 15;
    const int p    = (((blockIdx.x * 256 + threadIdx.x) >> 5) << 1) + (lane >> 4);
    const int b    = p >> 10;
    const int d    = p & (DI_ - 1);

    const float A   = -__expf(Alog[d * DS_ + n]);
    const float Dpd = Dp[d];
    float s = 0.f;

    for (int l = 0; l < L_; l++) {
        const int t = (b << 8) + l;
        const float dtv = g_dt[t * DI_ + d];
        const float xv  = g_xc[t * DI_ + d];
        const float q   = __expf(dtv * A);
        const float bm  = g_xdbl[t * XPD_ + DR_ + n];
        s = q * s + (dtv * xv) * bm;
        float v = s * g_xdbl[t * XPD_ + DR_ + DS_ + n];
        v += __shfl_xor_sync(0xFFFFFFFFu, v, 8);
        v += __shfl_xor_sync(0xFFFFFFFFu, v, 4);
        v += __shfl_xor_sync(0xFFFFFFFFu, v, 2);
        v += __shfl_xor_sync(0xFFFFFFFFu, v, 1);
        if (n == 0) {
            const float zv = g_xz[(size_t)t * (2 * DI_) + DI_ + d];
            const float yy = v + xv * Dpd;
            g_y[t * DI_ + d] = yy * (zv / (1.f + __expf(-zv)));
        }
    }
}

__global__ void ln_kernel(const float* __restrict__ gamma, const float* __restrict__ beta)
{
    __shared__ float red[128];
    const int b   = blockIdx.x;
    const int tid = threadIdx.x;   // 128
    const float* row = g_h + (size_t)((b + 1) * L_ - 1) * DM_;

    float v[4]; float s = 0.f;
#pragma unroll
    for (int i = 0; i < 4; i++) { v[i] = row[tid + i * 128]; s += v[i]; }
    red[tid] = s; __syncthreads();
    for (int o = 64; o > 0; o >>= 1) { if (tid < o) red[tid] += red[tid + o]; __syncthreads(); }
    const float mu = red[0] * (1.f / DM_);
    __syncthreads();

    float var = 0.f;
#pragma unroll
    for (int i = 0; i < 4; i++) { const float dd = v[i] - mu; var += dd * dd; }
    red[tid] = var; __syncthreads();
    for (int o = 64; o > 0; o >>= 1) { if (tid < o) red[tid] += red[tid + o]; __syncthreads(); }
    const float rstd = rsqrtf(red[0] * (1.f / DM_) + 1e-5f);

#pragma unroll
    for (int i = 0; i < 4; i++) {
        const int m = tid + i * 128;
        g_hn[b * DM_ + m] = (v[i] - mu) * rstd * gamma[m] + beta[m];
    }
}

__global__ void outproj_kernel(const float* __restrict__ ow, const float* __restrict__ ob,
                               float* __restrict__ out)
{
    __shared__ float sh[B_ * DM_];
    const int tid = threadIdx.x;  // 128
    for (int i = tid; i < B_ * DM_; i += 128) sh[i] = g_hn[i];
    __syncthreads();

    const int o = blockIdx.x * 128 + tid;
    float a0 = 0.f, a1 = 0.f, a2 = 0.f, a3 = 0.f;
    const float4* w4 = (const float4*)(ow + (size_t)o * DM_);
#pragma unroll 4
    for (int m4 = 0; m4 < DM_ / 4; m4++) {
        const float4 w = w4[m4];
        const int m = m4 * 4;
        a0 += sh[0 * DM_ + m] * w.x + sh[0 * DM_ + m + 1] * w.y + sh[0 * DM_ + m + 2] * w.z + sh[0 * DM_ + m + 3] * w.w;
        a1 += sh[1 * DM_ + m] * w.x + sh[1 * DM_ + m + 1] * w.y + sh[1 * DM_ + m + 2] * w.z + sh[1 * DM_ + m + 3] * w.w;
        a2 += sh[2 * DM_ + m] * w.x + sh[2 * DM_ + m + 1] * w.y + sh[2 * DM_ + m + 2] * w.z + sh[2 * DM_ + m + 3] * w.w;
        a3 += sh[3 * DM_ + m] * w.x + sh[3 * DM_ + m + 1] * w.y + sh[3 * DM_ + m + 2] * w.z + sh[3 * DM_ + m + 3] * w.w;
    }
    const float bo = ob[o];
    out[0 * IN_DIM_ + o] = a0 + bo;
    out[1 * IN_DIM_ + o] = a1 + bo;
    out[2 * IN_DIM_ + o] = a2 + bo;
    out[3 * IN_DIM_ + o] = a3 + bo;
}

// ---------------------------------------------------------------------------
extern "C" void kernel_launch(void* const* d_in, const int* in_sizes, int n_in,
                              void* d_out, int out_size)
{
    const float* x       = (const float*)d_in[0];
    const float* in_w    = (const float*)d_in[1];
    const float* in_b    = (const float*)d_in[2];
    const float* ln_g    = (const float*)d_in[3];
    const float* ln_b    = (const float*)d_in[4];
    const float* out_w   = (const float*)d_in[5];
    const float* out_b   = (const float*)d_in[6];
    const float* m_in_w  = (const float*)d_in[7];
    const float* conv_w  = (const float*)d_in[8];
    const float* conv_b  = (const float*)d_in[9];
    const float* xproj_w = (const float*)d_in[10];
    const float* dt_w    = (const float*)d_in[11];
    const float* dt_b    = (const float*)d_in[12];
    const float* A_log   = (const float*)d_in[13];
    const float* D_p     = (const float*)d_in[14];
    const float* m_out_w = (const float*)d_in[15];
    float* outp = (float*)d_out;

    float *ph, *pxz, *pxc, *pxdbl, *py, *ppart;
    cudaGetSymbolAddress((void**)&ph,    g_h);
    cudaGetSymbolAddress((void**)&pxz,   g_xz);
    cudaGetSymbolAddress((void**)&pxc,   g_xc);
    cudaGetSymbolAddress((void**)&pxdbl, g_xdbl);
    cudaGetSymbolAddress((void**)&py,    g_y);
    cudaGetSymbolAddress((void**)&ppart, g_part);

    // h = x @ in_w^T + in_b   (M=1024, N=512, K=16384, z=4 -> 256 CTAs)
    hgemm<<<dim3(DM_ / 64, T_ / 128, 4), 256>>>(
        x, in_w, ppart, T_, DM_, IN_DIM_, IN_DIM_ / 4);
    reduce_kernel<<<(T_ * DM_ + 255) / 256, 256>>>(ppart, ph, T_ * DM_, 4, in_b, DM_);

    for (int i = 0; i < DEPTH_; i++) {
        // xz = h @ m_in_w[i]^T   (M=1024, N=2048, K=512) -> 256 CTAs, direct
        hgemm<<<dim3(2 * DI_ / 64, T_ / 128, 1), 256>>>(
            ph, m_in_w + (size_t)i * 2 * DI_ * DM_, pxz, T_, 2 * DI_, DM_, DM_);

        // causal conv + silu
        conv_silu_kernel<<<T_ * DI_ / 256, 256>>>(conv_w + i * DI_ * DC_, conv_b + i * DI_);

        // xdbl = xc @ xproj_w[i]^T  (M=1024, N=64, K=1024, z=16 -> 128 CTAs)
        hgemm<<<dim3(1, T_ / 128, 16), 256>>>(
            pxc, xproj_w + (size_t)i * XPD_ * DI_, ppart, T_, XPD_, DI_, DI_ / 16);
        reduce_kernel<<<(T_ * XPD_ + 255) / 256, 256>>>(ppart, pxdbl, T_ * XPD_, 16, nullptr, XPD_);

        // dt = softplus(xdbl[:, :32] @ dt_w^T + dt_b)
        dt_kernel<<<dim3(DI_ / 256, T_), 256>>>(dt_w + (size_t)i * DI_ * DR_, dt_b + i * DI_);

        // selective scan + gating -> g_y
        scan_kernel<<<(B_ * DI_ * DS_) / 256, 256>>>(A_log + (size_t)i * DI_ * DS_, D_p + i * DI_);

        // h = y @ m_out_w[i]^T   (M=1024, N=512, K=1024, z=4 -> 256 CTAs)
        hgemm<<<dim3(DM_ / 64, T_ / 128, 4), 256>>>(
            py, m_out_w + (size_t)i * DM_ * DI_, ppart, T_, DM_, DI_, DI_ / 4);
        reduce_kernel<<<(T_ * DM_ + 255) / 256, 256>>>(ppart, ph, T_ * DM_, 4, nullptr, DM_);
    }

    // final layernorm on last token + output projection
    ln_kernel<<<B_, 128>>>(ln_g, ln_b);
    outproj_kernel<<<IN_DIM_ / 128, 128>>>(out_w, out_b, outp);
}